// round 8
// baseline (speedup 1.0000x reference)
#include <cuda_runtime.h>
#include <cstdint>

// NoiseMixModule: out = mask*A + (1-mask)*B, mask from double-argsort ranks of u.
//
// R6 = R4 structure tuned for 7 blocks/SM (wave quantization fix):
//   grid = 4096 is pinned by the float4 tiling (1024 rows/block, 256 thr).
//   5 blocks/SM -> 5.53 waves (8.5% tail loss). 7 blocks/SM -> 3.95 waves
//   (~1% loss). Achieved by: regs <= 36 (launch_bounds(256,7), 3+3+1 load
//   batches) and smem <= 32.5KB (byte masks: 29.7KB total).
//
//   phase 1: stage u slice into warp's smem strip (coalesced float4)
//   phase 2: SWAR nibble rank counts -> 7-bit byte mask per row in smem
//   phase 3: batched A/B blend, k-groups {3,3,1} (6 float4 in flight)

static constexpr int THREADS        = 256;
static constexpr int WARPS          = THREADS / 32;            // 8
static constexpr int ROWS_PER_WARP  = 128;
static constexpr int F4_PER_WARP    = ROWS_PER_WARP * 7 / 4;   // 224
static constexpr int ROWS_PER_BLOCK = ROWS_PER_WARP * WARPS;   // 1024
static constexpr int F4_PER_BLOCK   = F4_PER_WARP * WARPS;     // 1792

__global__ __launch_bounds__(THREADS, 7)
void noisemix_kernel(const float4* __restrict__ A,
                     const float4* __restrict__ B,
                     const float*  __restrict__ LAM,
                     const float4* __restrict__ U,
                     float4* __restrict__ OUT)
{
    __shared__ float         su[ROWS_PER_BLOCK * 7];   // 28 KB, per-warp strips
    __shared__ unsigned char smask[ROWS_PER_BLOCK];    //  1 KB, 7-bit masks

    const int warp = threadIdx.x >> 5;
    const int lane = threadIdx.x & 31;

    float*         suw    = su    + warp * ROWS_PER_WARP * 7;
    unsigned char* smaskw = smask + warp * ROWS_PER_WARP;

    const long wbase4   = (long)blockIdx.x * F4_PER_BLOCK + warp * F4_PER_WARP;
    const long wrowbase = (long)blockIdx.x * ROWS_PER_BLOCK + warp * ROWS_PER_WARP;

    // ---- phase 1: coalesced stage of this warp's u ----
    float4* suw4 = reinterpret_cast<float4*>(suw);
#pragma unroll
    for (int k = 0; k < 7; k++) {
        suw4[k * 32 + lane] = U[wbase4 + k * 32 + lane];
    }
    __syncwarp();

    // ---- phase 2: SWAR rank counts, 4 rows per lane ----
    // stable double-argsort rank: pair (a<b): u[a] <= u[b] -> b gains a
    // predecessor, else a does. cnt_d lives in nibble d of acc.
    // mask bit d = bit3 of nibble d of (acc + (8-nz)*0x01111111); compact the
    // 7 nibble-bits into one byte.
#pragma unroll
    for (int j = 0; j < 4; j++) {
        const int row = lane + j * 32;           // stride-7 LDS: conflict-free
        float uu[7];
#pragma unroll
        for (int d = 0; d < 7; d++) uu[d] = suw[row * 7 + d];

        const float lamv = LAM[wrowbase + row];  // coalesced 4B/lane
        const int   nz   = (int)floorf(7.0f * (1.0f - lamv));

        uint32_t acc = 0;
#pragma unroll
        for (int a = 0; a < 7; a++)
#pragma unroll
            for (int b = a + 1; b < 7; b++)
                acc += (uu[a] <= uu[b]) ? (1u << (4 * b)) : (1u << (4 * a));

        const uint32_t t = ((acc + (uint32_t)(8 - nz) * 0x01111111u) >> 3)
                           & 0x01111111u;        // bit 4d = mask bit d
        unsigned m = (t & 1u)
                   | ((t >> 3)  & 2u)
                   | ((t >> 6)  & 4u)
                   | ((t >> 9)  & 8u)
                   | ((t >> 12) & 16u)
                   | ((t >> 15) & 32u)
                   | ((t >> 18) & 64u);
        smaskw[row] = (unsigned char)m;
    }
    __syncwarp();

    // ---- phase 3: batched A/B stream + blend, k-groups {3,3,1} ----
#pragma unroll
    for (int g = 0; g < 3; g++) {
        const int k0 = (g == 0) ? 0 : (g == 1) ? 3 : 6;
        const int kn = (g == 2) ? 1 : 3;

        float4 a[3], b[3];
#pragma unroll
        for (int k = 0; k < 3; k++) {
            if (k < kn) {
                const long idx4 = wbase4 + (k0 + k) * 32 + lane;
                a[k] = A[idx4];
                b[k] = B[idx4];
            }
        }

#pragma unroll
        for (int k = 0; k < 3; k++) {
            if (k < kn) {
                int le  = ((k0 + k) * 32 + lane) * 4;   // element idx in warp tile
                int row = le / 7;
                int d   = le - row * 7;

                unsigned m = smaskw[row];
                float4 o;
                o.x = (m >> d) & 1u ? a[k].x : b[k].x;
                d++; if (d == 7) { d = 0; row++; m = smaskw[row]; }
                o.y = (m >> d) & 1u ? a[k].y : b[k].y;
                d++; if (d == 7) { d = 0; row++; m = smaskw[row]; }
                o.z = (m >> d) & 1u ? a[k].z : b[k].z;
                d++; if (d == 7) { d = 0; row++; m = smaskw[row]; }
                o.w = (m >> d) & 1u ? a[k].w : b[k].w;

                OUT[wbase4 + (k0 + k) * 32 + lane] = o;
            }
        }
    }
}

extern "C" void kernel_launch(void* const* d_in, const int* in_sizes, int n_in,
                              void* d_out, int out_size)
{
    const float4* A   = (const float4*)d_in[0];   // noise_A [B,7]
    const float4* Bp  = (const float4*)d_in[1];   // noise_B [B,7]
    const float*  LAM = (const float*)d_in[2];    // lam [B]
    const float4* U   = (const float4*)d_in[3];   // u [B,7]
    float4* OUT = (float4*)d_out;

    const int Brows  = in_sizes[2];                // 4194304
    const int blocks = Brows / ROWS_PER_BLOCK;     // 4096

    noisemix_kernel<<<blocks, THREADS>>>(A, Bp, LAM, U, OUT);
}

// round 9
// speedup vs baseline: 1.1656x; 1.1656x over previous
#include <cuda_runtime.h>
#include <cstdint>

// NoiseMixModule: out = mask*A + (1-mask)*B, mask from double-argsort ranks of u.
//
// R9 = R4 champion + load/compute overlap:
//   - issue u loads (7x LDG.128) then IMMEDIATELY group-1 A/B loads
//     (8x LDG.128) -> 15 loads in flight per warp before any compute
//   - phase 2 (SWAR rank masks) executes under the outstanding A/B loads
//   - blend/store group 1, then load+blend group 2 (k=4..6)
//   regs ~55-60 -> 4 blocks/SM, 32 warps, 6.92 waves (92%-full tail).
//   NOTE: no occupancy cap in launch_bounds — reg budgets <=32 make ptxas
//   serialize the batches (measured: R5/R6 regressions to ~86us).

static constexpr int THREADS        = 256;
static constexpr int WARPS          = THREADS / 32;            // 8
static constexpr int ROWS_PER_WARP  = 128;
static constexpr int F4_PER_WARP    = ROWS_PER_WARP * 7 / 4;   // 224
static constexpr int ROWS_PER_BLOCK = ROWS_PER_WARP * WARPS;   // 1024
static constexpr int F4_PER_BLOCK   = F4_PER_WARP * WARPS;     // 1792

__global__ __launch_bounds__(THREADS)
void noisemix_kernel(const float4* __restrict__ A,
                     const float4* __restrict__ B,
                     const float*  __restrict__ LAM,
                     const float4* __restrict__ U,
                     float4* __restrict__ OUT)
{
    __shared__ float    su[ROWS_PER_BLOCK * 7];     // 28 KB, per-warp strips
    __shared__ uint32_t smask[ROWS_PER_BLOCK];      //  4 KB, SWAR mask words

    const int warp = threadIdx.x >> 5;
    const int lane = threadIdx.x & 31;

    float*    suw    = su    + warp * ROWS_PER_WARP * 7;
    uint32_t* smaskw = smask + warp * ROWS_PER_WARP;

    const long wbase4   = (long)blockIdx.x * F4_PER_BLOCK + warp * F4_PER_WARP;
    const long wrowbase = (long)blockIdx.x * ROWS_PER_BLOCK + warp * ROWS_PER_WARP;

    // ---- phase 1a: issue u loads (coalesced float4 -> smem) ----
    float4* suw4 = reinterpret_cast<float4*>(suw);
#pragma unroll
    for (int k = 0; k < 7; k++) {
        suw4[k * 32 + lane] = U[wbase4 + k * 32 + lane];
    }

    // ---- phase 1b: issue group-1 A/B loads BEFORE computing masks ----
    // These are independent of u; their latency is hidden under phase 2.
    float4 a1[4], b1[4];
#pragma unroll
    for (int k = 0; k < 4; k++) {
        const long idx4 = wbase4 + k * 32 + lane;
        a1[k] = A[idx4];
        b1[k] = B[idx4];
    }

    __syncwarp();

    // ---- phase 2: SWAR rank counts, 4 rows per lane ----
    // stable double-argsort rank: pair (a<b): u[a] <= u[b] -> b gains a
    // predecessor, else a does. cnt_d lives in nibble d of acc.
    // mask bit d = bit3 of nibble d of (acc + (8-nz)*0x01111111).
#pragma unroll
    for (int j = 0; j < 4; j++) {
        const int row = lane + j * 32;           // stride-7 LDS: conflict-free
        float uu[7];
#pragma unroll
        for (int d = 0; d < 7; d++) uu[d] = suw[row * 7 + d];

        const float lamv = LAM[wrowbase + row];  // coalesced 4B/lane
        const int   nz   = (int)floorf(7.0f * (1.0f - lamv));

        uint32_t acc = 0;
#pragma unroll
        for (int a = 0; a < 7; a++)
#pragma unroll
            for (int b = a + 1; b < 7; b++)
                acc += (uu[a] <= uu[b]) ? (1u << (4 * b)) : (1u << (4 * a));

        smaskw[row] = acc + (uint32_t)(8 - nz) * 0x01111111u;
    }
    __syncwarp();

    // ---- phase 3a: blend + store group 1 (k = 0..3) ----
#pragma unroll
    for (int k = 0; k < 4; k++) {
        int le  = (k * 32 + lane) * 4;          // element idx within warp tile
        int row = le / 7;
        int d   = le - row * 7;

        uint32_t m = smaskw[row];
        float4 o;
        o.x = (m >> (4 * d + 3)) & 1u ? a1[k].x : b1[k].x;
        d++; if (d == 7) { d = 0; row++; m = smaskw[row]; }
        o.y = (m >> (4 * d + 3)) & 1u ? a1[k].y : b1[k].y;
        d++; if (d == 7) { d = 0; row++; m = smaskw[row]; }
        o.z = (m >> (4 * d + 3)) & 1u ? a1[k].z : b1[k].z;
        d++; if (d == 7) { d = 0; row++; m = smaskw[row]; }
        o.w = (m >> (4 * d + 3)) & 1u ? a1[k].w : b1[k].w;

        OUT[wbase4 + k * 32 + lane] = o;
    }

    // ---- phase 3b: load + blend + store group 2 (k = 4..6) ----
    float4 a2[3], b2[3];
#pragma unroll
    for (int k = 0; k < 3; k++) {
        const long idx4 = wbase4 + (4 + k) * 32 + lane;
        a2[k] = A[idx4];
        b2[k] = B[idx4];
    }

#pragma unroll
    for (int k = 0; k < 3; k++) {
        int le  = ((4 + k) * 32 + lane) * 4;
        int row = le / 7;
        int d   = le - row * 7;

        uint32_t m = smaskw[row];
        float4 o;
        o.x = (m >> (4 * d + 3)) & 1u ? a2[k].x : b2[k].x;
        d++; if (d == 7) { d = 0; row++; m = smaskw[row]; }
        o.y = (m >> (4 * d + 3)) & 1u ? a2[k].y : b2[k].y;
        d++; if (d == 7) { d = 0; row++; m = smaskw[row]; }
        o.z = (m >> (4 * d + 3)) & 1u ? a2[k].z : b2[k].z;
        d++; if (d == 7) { d = 0; row++; m = smaskw[row]; }
        o.w = (m >> (4 * d + 3)) & 1u ? a2[k].w : b2[k].w;

        OUT[wbase4 + (4 + k) * 32 + lane] = o;
    }
}

extern "C" void kernel_launch(void* const* d_in, const int* in_sizes, int n_in,
                              void* d_out, int out_size)
{
    const float4* A   = (const float4*)d_in[0];   // noise_A [B,7]
    const float4* Bp  = (const float4*)d_in[1];   // noise_B [B,7]
    const float*  LAM = (const float*)d_in[2];    // lam [B]
    const float4* U   = (const float4*)d_in[3];   // u [B,7]
    float4* OUT = (float4*)d_out;

    const int Brows  = in_sizes[2];                // 4194304
    const int blocks = Brows / ROWS_PER_BLOCK;     // 4096

    noisemix_kernel<<<blocks, THREADS>>>(A, Bp, LAM, U, OUT);
}